// round 9
// baseline (speedup 1.0000x reference)
#include <cuda_runtime.h>
#include <cuda_bf16.h>

// out = softmax(x1 @ x2^T * SCALE) @ x2,  B=16, L=2048, D=128, fp32.
// mma.sync bf16 (sm_80-baseline PTX), 3-term error-compensated split,
// single-pass softmax (|s| <= ~7 -> exp fp32-safe).
// R9: BQ=64/BK=32, 4 warps, 108KB smem -> 2 CTAs/SM so one CTA's MMAs
// cover the other's softmax/convert/barrier gaps.

#define BQ 64
#define BK 32
#define DIM 128
#define LSEQ 2048
#define NKT (LSEQ / BK)   // 64
#define SCALE 0.08838834764831845f

// smem layout (bytes). Q/K rows 272B (17x16B), Vt rows 80B (5x16B):
// 16B-unit stride odd -> ldmatrix phases conflict-free.
#define QROW 272
#define KROW 272
#define VROW 80
#define SM_QH 0
#define SM_QL 17408
#define SM_KV 34816
#define KV_KH 0
#define KV_KL 8704
#define KV_VH 17408
#define KV_VL 27648
#define KVBUF 37888
#define SMEM_TOTAL (SM_KV + 2 * KVBUF)   // 110592 bytes

static __device__ __forceinline__ unsigned s2u(const void* p) {
    unsigned a;
    asm("{ .reg .u64 t; cvta.to.shared.u64 t, %1; cvt.u32.u64 %0, t; }" : "=r"(a) : "l"(p));
    return a;
}

// split x into bf16 hi + bf16 lo (x ~= hi + lo), two values packed per b32
static __device__ __forceinline__ void split2(float x0, float x1,
                                              unsigned& hp, unsigned& lp) {
    __nv_bfloat162 h = __floats2bfloat162_rn(x0, x1);
    hp = *reinterpret_cast<unsigned*>(&h);
    float h0 = __uint_as_float(hp << 16);
    float h1 = __uint_as_float(hp & 0xffff0000u);
    __nv_bfloat162 l = __floats2bfloat162_rn(x0 - h0, x1 - h1);
    lp = *reinterpret_cast<unsigned*>(&l);
}

static __device__ __forceinline__ void ldsm4(unsigned& r0, unsigned& r1,
                                             unsigned& r2, unsigned& r3, unsigned a) {
    asm volatile("ldmatrix.sync.aligned.m8n8.x4.shared.b16 {%0,%1,%2,%3}, [%4];"
                 : "=r"(r0), "=r"(r1), "=r"(r2), "=r"(r3) : "r"(a));
}

static __device__ __forceinline__ void mma16816(float* d,
        unsigned a0, unsigned a1, unsigned a2, unsigned a3,
        unsigned b0, unsigned b1) {
    asm volatile(
        "mma.sync.aligned.m16n8k16.row.col.f32.bf16.bf16.f32 "
        "{%0,%1,%2,%3}, {%4,%5,%6,%7}, {%8,%9}, {%0,%1,%2,%3};"
        : "+f"(d[0]), "+f"(d[1]), "+f"(d[2]), "+f"(d[3])
        : "r"(a0), "r"(a1), "r"(a2), "r"(a3), "r"(b0), "r"(b1));
}

// Each thread owns a 4(kpos) x 8(d) block of the 32x128 K/V tile. 128 threads.
static __device__ __forceinline__ void kv_load(const float* kvbase, int kt, int tid,
                                               float4* kvr) {
    int kb = (tid & 7) * 4, db = (tid >> 3) * 8;
    const float* p = kvbase + ((size_t)kt * BK + kb) * DIM + db;
    #pragma unroll
    for (int j = 0; j < 4; j++) {
        kvr[2 * j]     = ((const float4*)(p + j * DIM))[0];
        kvr[2 * j + 1] = ((const float4*)(p + j * DIM))[1];
    }
}

static __device__ __forceinline__ void kv_store(char* buf, int tid, const float4* kvr) {
    int kb = (tid & 7) * 4, db = (tid >> 3) * 8;
    unsigned kh[4][4], kl[4][4];
    #pragma unroll
    for (int j = 0; j < 4; j++) {
        split2(kvr[2 * j].x,     kvr[2 * j].y,     kh[j][0], kl[j][0]);
        split2(kvr[2 * j].z,     kvr[2 * j].w,     kh[j][1], kl[j][1]);
        split2(kvr[2 * j + 1].x, kvr[2 * j + 1].y, kh[j][2], kl[j][2]);
        split2(kvr[2 * j + 1].z, kvr[2 * j + 1].w, kh[j][3], kl[j][3]);
        *(uint4*)(buf + KV_KH + (kb + j) * KROW + db * 2) =
            make_uint4(kh[j][0], kh[j][1], kh[j][2], kh[j][3]);
        *(uint4*)(buf + KV_KL + (kb + j) * KROW + db * 2) =
            make_uint4(kl[j][0], kl[j][1], kl[j][2], kl[j][3]);
    }
    // transposed V^T[d][kpos], 4 kpos packed per STS.64
    #pragma unroll
    for (int d = 0; d < 8; d++) {
        int p = d >> 1, sh = (d & 1) * 16;
        unsigned e0 = (kh[0][p] >> sh) & 0xffffu;
        unsigned e1 = (kh[1][p] >> sh) & 0xffffu;
        unsigned e2 = (kh[2][p] >> sh) & 0xffffu;
        unsigned e3 = (kh[3][p] >> sh) & 0xffffu;
        *(uint2*)(buf + KV_VH + (db + d) * VROW + kb * 2) =
            make_uint2(e0 | (e1 << 16), e2 | (e3 << 16));
        e0 = (kl[0][p] >> sh) & 0xffffu;
        e1 = (kl[1][p] >> sh) & 0xffffu;
        e2 = (kl[2][p] >> sh) & 0xffffu;
        e3 = (kl[3][p] >> sh) & 0xffffu;
        *(uint2*)(buf + KV_VL + (db + d) * VROW + kb * 2) =
            make_uint2(e0 | (e1 << 16), e2 | (e3 << 16));
    }
}

__global__ void __launch_bounds__(128, 2)
attn_mma_kernel(const float* __restrict__ x1,
                const float* __restrict__ x2,
                float* __restrict__ out) {
    extern __shared__ char smem[];
    const unsigned sb = s2u(smem);
    const int tid = threadIdx.x;
    const int w = tid >> 5, lane = tid & 31;
    const int g = lane >> 2, t4 = lane & 3;
    const int b = blockIdx.y, qt = blockIdx.x;

    // ---- Q prologue: load, scale, split to hi/lo bf16 in smem ----
    {
        int r = tid >> 1;                 // 0..63
        int c0 = (tid & 1) * 64;
        const float* q = x1 + ((size_t)b * LSEQ + (size_t)qt * BQ + r) * DIM + c0;
        char* qh = smem + SM_QH + r * QROW + c0 * 2;
        char* ql = smem + SM_QL + r * QROW + c0 * 2;
        #pragma unroll
        for (int i = 0; i < 8; i++) {
            float4 v0 = ((const float4*)q)[2 * i];
            float4 v1 = ((const float4*)q)[2 * i + 1];
            v0.x *= SCALE; v0.y *= SCALE; v0.z *= SCALE; v0.w *= SCALE;
            v1.x *= SCALE; v1.y *= SCALE; v1.z *= SCALE; v1.w *= SCALE;
            unsigned h[4], l[4];
            split2(v0.x, v0.y, h[0], l[0]);
            split2(v0.z, v0.w, h[1], l[1]);
            split2(v1.x, v1.y, h[2], l[2]);
            split2(v1.z, v1.w, h[3], l[3]);
            *(uint4*)(qh + i * 16) = make_uint4(h[0], h[1], h[2], h[3]);
            *(uint4*)(ql + i * 16) = make_uint4(l[0], l[1], l[2], l[3]);
        }
    }

    const float* kvbase = x2 + (size_t)b * LSEQ * DIM;
    float4 kvr[8];
    kv_load(kvbase, 0, tid, kvr);
    kv_store(smem + SM_KV, tid, kvr);
    __syncthreads();

    // per-lane ldmatrix offsets
    const unsigned aoff = (unsigned)((16 * w + (lane & 15)) * QROW + (lane >> 4) * 16);
    const unsigned aQH = sb + SM_QH + aoff;
    const unsigned aQL = sb + SM_QL + aoff;
    // merged hi/lo B-fragment x4: lanes 0-15 -> hi region, lanes 16-31 -> lo
    const unsigned hl = (lane >> 4) & 1;
    const unsigned koff = (unsigned)((lane & 7) * KROW + ((lane >> 3) & 1) * 16
                                     + hl * (KV_KL - KV_KH));
    const unsigned voff = (unsigned)((lane & 7) * VROW + ((lane >> 3) & 1) * 16
                                     + hl * (KV_VL - KV_VH));

    float O[16][4];
    #pragma unroll
    for (int jj = 0; jj < 16; jj++)
        #pragma unroll
        for (int e = 0; e < 4; e++) O[jj][e] = 0.0f;
    float lsum0 = 0.0f, lsum1 = 0.0f;

    #pragma unroll 1
    for (int kt = 0; kt < NKT; kt++) {
        const unsigned bufb = sb + SM_KV + (unsigned)(kt & 1) * KVBUF;
        const unsigned aK = bufb + KV_KH + koff;
        const unsigned aV = bufb + KV_VH + voff;

        if (kt + 1 < NKT) kv_load(kvbase, kt + 1, tid, kvr);  // prefetch (LDG)

        // ---- S = Q @ K^T (16x32 per warp), 3-term split ----
        float S[4][4];
        #pragma unroll
        for (int jj = 0; jj < 4; jj++)
            #pragma unroll
            for (int e = 0; e < 4; e++) S[jj][e] = 0.0f;

        #pragma unroll
        for (int ks = 0; ks < 8; ks++) {
            unsigned ah0, ah1, ah2, ah3, al0, al1, al2, al3;
            ldsm4(ah0, ah1, ah2, ah3, aQH + ks * 32);
            ldsm4(al0, al1, al2, al3, aQL + ks * 32);
            #pragma unroll
            for (int jj = 0; jj < 4; jj++) {
                unsigned bh0, bh1, bl0, bl1;
                ldsm4(bh0, bh1, bl0, bl1, aK + jj * (8 * KROW) + ks * 32);
                mma16816(S[jj], ah0, ah1, ah2, ah3, bh0, bh1);
                mma16816(S[jj], al0, al1, al2, al3, bh0, bh1);
                mma16816(S[jj], ah0, ah1, ah2, ah3, bl0, bl1);
            }
        }

        // ---- exp, row-sum accumulation, repack to PV A-fragments ----
        unsigned pH[2][4], pL[2][4];
        #pragma unroll
        for (int jj = 0; jj < 4; jj++) {
            float p0 = __expf(S[jj][0]), p1 = __expf(S[jj][1]);
            float p2 = __expf(S[jj][2]), p3 = __expf(S[jj][3]);
            lsum0 += p0 + p1;
            lsum1 += p2 + p3;
            int j = jj >> 1, hh = (jj & 1) * 2;
            split2(p0, p1, pH[j][hh],     pL[j][hh]);
            split2(p2, p3, pH[j][hh + 1], pL[j][hh + 1]);
        }

        // ---- O += P @ V (16x128 per warp), 3-term split ----
        #pragma unroll
        for (int j = 0; j < 2; j++) {
            #pragma unroll
            for (int jj = 0; jj < 16; jj++) {
                unsigned bh0, bh1, bl0, bl1;
                ldsm4(bh0, bh1, bl0, bl1, aV + jj * (8 * VROW) + j * 32);
                mma16816(O[jj], pH[j][0], pH[j][1], pH[j][2], pH[j][3], bh0, bh1);
                mma16816(O[jj], pL[j][0], pL[j][1], pL[j][2], pL[j][3], bh0, bh1);
                mma16816(O[jj], pH[j][0], pH[j][1], pH[j][2], pH[j][3], bl0, bl1);
            }
        }

        // conversion for next tile issues into the tensor-drain tail
        if (kt + 1 < NKT)
            kv_store(smem + SM_KV + (size_t)((kt + 1) & 1) * KVBUF, tid, kvr);
        __syncthreads();
    }

    // ---- finalize row sums (reduce over the 4 lanes of each row group) ----
    lsum0 += __shfl_xor_sync(0xffffffffu, lsum0, 1);
    lsum0 += __shfl_xor_sync(0xffffffffu, lsum0, 2);
    lsum1 += __shfl_xor_sync(0xffffffffu, lsum1, 1);
    lsum1 += __shfl_xor_sync(0xffffffffu, lsum1, 2);
    float inv0 = 1.0f / lsum0, inv1 = 1.0f / lsum1;

    float* o0 = out + ((size_t)b * LSEQ + (size_t)qt * BQ + 16 * w + g) * DIM;
    #pragma unroll
    for (int jj = 0; jj < 16; jj++) {
        int col = 8 * jj + 2 * t4;
        *(float2*)(o0 + col) = make_float2(O[jj][0] * inv0, O[jj][1] * inv0);
        *(float2*)(o0 + 8 * DIM + col) = make_float2(O[jj][2] * inv1, O[jj][3] * inv1);
    }
}

extern "C" void kernel_launch(void* const* d_in, const int* in_sizes, int n_in,
                              void* d_out, int out_size) {
    const float* x1 = (const float*)d_in[0];
    const float* x2 = (const float*)d_in[1];
    float* out = (float*)d_out;

    cudaFuncSetAttribute(attn_mma_kernel,
                         cudaFuncAttributeMaxDynamicSharedMemorySize, SMEM_TOTAL);

    dim3 grid(LSEQ / BQ, 16);   // 32 q-tiles x 16 batches = 512 CTAs
    attn_mma_kernel<<<grid, 128, SMEM_TOTAL>>>(x1, x2, out);
}

// round 10
// speedup vs baseline: 1.4656x; 1.4656x over previous
#include <cuda_runtime.h>
#include <cuda_bf16.h>

// out = softmax(x1 @ x2^T * SCALE) @ x2,  B=16, L=2048, D=128, fp32.
// mma.sync bf16 (sm_80-baseline PTX), 3-term error-compensated split,
// single-pass softmax (|s| <= ~7 -> exp fp32-safe).
// R10: V==K -> PV B-fragments via ldmatrix.x4.trans from the K tiles
// (no Vt build, no Vt smem); software-pipelined fragment loads.

#define BQ 128
#define BK 64
#define DIM 128
#define LSEQ 2048
#define NKT (LSEQ / BK)
#define SCALE 0.08838834764831845f

// smem layout (bytes). K rows 272B (17x16B): odd 16B stride -> ldmatrix
// phases conflict-free (both normal and trans).
#define QROW 272
#define KROW 272
#define SM_QH 0
#define SM_QL 17408        // 64 rows would be 17408.. Q has 128 rows: see below
#undef SM_QL
#define SM_QL 34816
#define SM_KV 69632
#define KV_KH 0
#define KV_KL 17408
#define KVBUF 34816
#define SMEM_TOTAL (SM_KV + 2 * KVBUF)   // 139264 bytes

static __device__ __forceinline__ unsigned s2u(const void* p) {
    unsigned a;
    asm("{ .reg .u64 t; cvta.to.shared.u64 t, %1; cvt.u32.u64 %0, t; }" : "=r"(a) : "l"(p));
    return a;
}

// split x into bf16 hi + bf16 lo (x ~= hi + lo), two values packed per b32
static __device__ __forceinline__ void split2(float x0, float x1,
                                              unsigned& hp, unsigned& lp) {
    __nv_bfloat162 h = __floats2bfloat162_rn(x0, x1);
    hp = *reinterpret_cast<unsigned*>(&h);
    float h0 = __uint_as_float(hp << 16);
    float h1 = __uint_as_float(hp & 0xffff0000u);
    __nv_bfloat162 l = __floats2bfloat162_rn(x0 - h0, x1 - h1);
    lp = *reinterpret_cast<unsigned*>(&l);
}

static __device__ __forceinline__ void ldsm4(unsigned* r, unsigned a) {
    asm volatile("ldmatrix.sync.aligned.m8n8.x4.shared.b16 {%0,%1,%2,%3}, [%4];"
                 : "=r"(r[0]), "=r"(r[1]), "=r"(r[2]), "=r"(r[3]) : "r"(a));
}

static __device__ __forceinline__ void ldsm4t(unsigned* r, unsigned a) {
    asm volatile("ldmatrix.sync.aligned.m8n8.x4.trans.shared.b16 {%0,%1,%2,%3}, [%4];"
                 : "=r"(r[0]), "=r"(r[1]), "=r"(r[2]), "=r"(r[3]) : "r"(a));
}

static __device__ __forceinline__ void mma16816(float* d,
        unsigned a0, unsigned a1, unsigned a2, unsigned a3,
        unsigned b0, unsigned b1) {
    asm volatile(
        "mma.sync.aligned.m16n8k16.row.col.f32.bf16.bf16.f32 "
        "{%0,%1,%2,%3}, {%4,%5,%6,%7}, {%8,%9}, {%0,%1,%2,%3};"
        : "+f"(d[0]), "+f"(d[1]), "+f"(d[2]), "+f"(d[3])
        : "r"(a0), "r"(a1), "r"(a2), "r"(a3), "r"(b0), "r"(b1));
}

// Each thread owns a 4(kpos) x 8(d) block of the 64x128 K tile.
static __device__ __forceinline__ void kv_load(const float* kvbase, int kt, int tid,
                                               float4* kvr) {
    int kb = (tid & 15) * 4, db = (tid >> 4) * 8;
    const float* p = kvbase + ((size_t)kt * BK + kb) * DIM + db;
    #pragma unroll
    for (int j = 0; j < 4; j++) {
        kvr[2 * j]     = ((const float4*)(p + j * DIM))[0];
        kvr[2 * j + 1] = ((const float4*)(p + j * DIM))[1];
    }
}

// K-only store (V is the same data, read back with ldmatrix.trans)
static __device__ __forceinline__ void kv_store(char* buf, int tid, const float4* kvr) {
    int kb = (tid & 15) * 4, db = (tid >> 4) * 8;
    #pragma unroll
    for (int j = 0; j < 4; j++) {
        unsigned h[4], l[4];
        split2(kvr[2 * j].x,     kvr[2 * j].y,     h[0], l[0]);
        split2(kvr[2 * j].z,     kvr[2 * j].w,     h[1], l[1]);
        split2(kvr[2 * j + 1].x, kvr[2 * j + 1].y, h[2], l[2]);
        split2(kvr[2 * j + 1].z, kvr[2 * j + 1].w, h[3], l[3]);
        *(uint4*)(buf + KV_KH + (kb + j) * KROW + db * 2) =
            make_uint4(h[0], h[1], h[2], h[3]);
        *(uint4*)(buf + KV_KL + (kb + j) * KROW + db * 2) =
            make_uint4(l[0], l[1], l[2], l[3]);
    }
}

__global__ void __launch_bounds__(256, 1)
attn_mma_kernel(const float* __restrict__ x1,
                const float* __restrict__ x2,
                float* __restrict__ out) {
    extern __shared__ char smem[];
    const unsigned sb = s2u(smem);
    const int tid = threadIdx.x;
    const int w = tid >> 5, lane = tid & 31;
    const int g = lane >> 2, t4 = lane & 3;
    const int b = blockIdx.y, qt = blockIdx.x;

    // ---- Q prologue: load, scale, split to hi/lo bf16 in smem ----
    {
        int r = tid >> 1;
        int c0 = (tid & 1) * 64;
        const float* q = x1 + ((size_t)b * LSEQ + (size_t)qt * BQ + r) * DIM + c0;
        char* qh = smem + SM_QH + r * QROW + c0 * 2;
        char* ql = smem + SM_QL + r * QROW + c0 * 2;
        #pragma unroll
        for (int i = 0; i < 8; i++) {
            float4 v0 = ((const float4*)q)[2 * i];
            float4 v1 = ((const float4*)q)[2 * i + 1];
            v0.x *= SCALE; v0.y *= SCALE; v0.z *= SCALE; v0.w *= SCALE;
            v1.x *= SCALE; v1.y *= SCALE; v1.z *= SCALE; v1.w *= SCALE;
            unsigned h[4], l[4];
            split2(v0.x, v0.y, h[0], l[0]);
            split2(v0.z, v0.w, h[1], l[1]);
            split2(v1.x, v1.y, h[2], l[2]);
            split2(v1.z, v1.w, h[3], l[3]);
            *(uint4*)(qh + i * 16) = make_uint4(h[0], h[1], h[2], h[3]);
            *(uint4*)(ql + i * 16) = make_uint4(l[0], l[1], l[2], l[3]);
        }
    }

    const float* kvbase = x2 + (size_t)b * LSEQ * DIM;
    float4 kvr[8];
    kv_load(kvbase, 0, tid, kvr);
    kv_store(smem + SM_KV, tid, kvr);
    __syncthreads();

    // per-lane ldmatrix offsets
    const unsigned aoff = (unsigned)((16 * w + (lane & 15)) * QROW + (lane >> 4) * 16);
    const unsigned aQH = sb + SM_QH + aoff;
    const unsigned aQL = sb + SM_QL + aoff;
    // QK B: merged hi/lo x4 (lanes 0-15 -> KH rows, 16-31 -> KL rows)
    const unsigned hl = (lane >> 4) & 1;
    const unsigned koff = (unsigned)((lane & 7) * KROW + ((lane >> 3) & 1) * 16
                                     + hl * (KV_KL - KV_KH));
    // PV B via trans: row = lane&15, col-block (lane>>4)*16 bytes
    const unsigned voff = (unsigned)((lane & 15) * KROW + (lane >> 4) * 16);

    float O[16][4];
    #pragma unroll
    for (int jj = 0; jj < 16; jj++)
        #pragma unroll
        for (int e = 0; e < 4; e++) O[jj][e] = 0.0f;
    float lsum0 = 0.0f, lsum1 = 0.0f;

    #pragma unroll 1
    for (int kt = 0; kt < NKT; kt++) {
        const unsigned bufb = sb + SM_KV + (unsigned)(kt & 1) * KVBUF;
        const unsigned aK = bufb + KV_KH + koff;
        const unsigned aVH = bufb + KV_KH + voff;
        const unsigned aVL = bufb + KV_KL + voff;

        if (kt + 1 < NKT) kv_load(kvbase, kt + 1, tid, kvr);  // prefetch (LDG)

        // ---- S = Q @ K^T (16x64 per warp), 3-term split, pipelined ----
        float S[8][4];
        #pragma unroll
        for (int jj = 0; jj < 8; jj++)
            #pragma unroll
            for (int e = 0; e < 4; e++) S[jj][e] = 0.0f;

        unsigned ah[2][4], al[2][4], bq[2][4];
        ldsm4(ah[0], aQH);
        ldsm4(al[0], aQL);
        ldsm4(bq[0], aK);
        #pragma unroll
        for (int ks = 0; ks < 8; ks++) {
            const int ac = ks & 1;
            if (ks < 7) {
                ldsm4(ah[ac ^ 1], aQH + (ks + 1) * 32);
                ldsm4(al[ac ^ 1], aQL + (ks + 1) * 32);
            }
            #pragma unroll
            for (int jj = 0; jj < 8; jj++) {
                const int bc = (ks * 8 + jj) & 1;
                if (jj < 7)
                    ldsm4(bq[bc ^ 1], aK + (jj + 1) * (8 * KROW) + ks * 32);
                else if (ks < 7)
                    ldsm4(bq[bc ^ 1], aK + (ks + 1) * 32);
                mma16816(S[jj], ah[ac][0], ah[ac][1], ah[ac][2], ah[ac][3],
                         bq[bc][0], bq[bc][1]);
                mma16816(S[jj], al[ac][0], al[ac][1], al[ac][2], al[ac][3],
                         bq[bc][0], bq[bc][1]);
                mma16816(S[jj], ah[ac][0], ah[ac][1], ah[ac][2], ah[ac][3],
                         bq[bc][2], bq[bc][3]);
            }
        }

        // ---- exp, row-sum accumulation, repack to PV A-fragments ----
        unsigned pH[4][4], pL[4][4];
        #pragma unroll
        for (int jj = 0; jj < 8; jj++) {
            float p0 = __expf(S[jj][0]), p1 = __expf(S[jj][1]);
            float p2 = __expf(S[jj][2]), p3 = __expf(S[jj][3]);
            lsum0 += p0 + p1;
            lsum1 += p2 + p3;
            int j = jj >> 1, hh = (jj & 1) * 2;
            split2(p0, p1, pH[j][hh],     pL[j][hh]);
            split2(p2, p3, pH[j][hh + 1], pL[j][hh + 1]);
        }

        // ---- O += P @ V (16x128 per warp), V read from K tiles via trans ----
        {
            unsigned bh[2][4], bl[2][4];
            ldsm4t(bh[0], aVH);
            ldsm4t(bl[0], aVL);
            #pragma unroll
            for (int j = 0; j < 4; j++) {
                #pragma unroll
                for (int jjp = 0; jjp < 8; jjp++) {
                    const int cur = (j * 8 + jjp) & 1;
                    int nj = j, njp = jjp + 1;
                    if (njp == 8) { njp = 0; nj = j + 1; }
                    if (nj < 4) {
                        unsigned na = (unsigned)(nj * 16 * KROW + njp * 32);
                        ldsm4t(bh[cur ^ 1], aVH + na);
                        ldsm4t(bl[cur ^ 1], aVL + na);
                    }
                    float* O0 = O[2 * jjp];
                    float* O1 = O[2 * jjp + 1];
                    mma16816(O0, pH[j][0], pH[j][1], pH[j][2], pH[j][3],
                             bh[cur][0], bh[cur][1]);
                    mma16816(O0, pL[j][0], pL[j][1], pL[j][2], pL[j][3],
                             bh[cur][0], bh[cur][1]);
                    mma16816(O0, pH[j][0], pH[j][1], pH[j][2], pH[j][3],
                             bl[cur][0], bl[cur][1]);
                    mma16816(O1, pH[j][0], pH[j][1], pH[j][2], pH[j][3],
                             bh[cur][2], bh[cur][3]);
                    mma16816(O1, pL[j][0], pL[j][1], pL[j][2], pL[j][3],
                             bh[cur][2], bh[cur][3]);
                    mma16816(O1, pH[j][0], pH[j][1], pH[j][2], pH[j][3],
                             bl[cur][2], bl[cur][3]);
                }
            }
        }

        // conversion for next tile issues into the tensor-drain tail
        if (kt + 1 < NKT)
            kv_store(smem + SM_KV + (size_t)((kt + 1) & 1) * KVBUF, tid, kvr);
        __syncthreads();
    }

    // ---- finalize row sums (reduce over the 4 lanes of each row group) ----
    lsum0 += __shfl_xor_sync(0xffffffffu, lsum0, 1);
    lsum0 += __shfl_xor_sync(0xffffffffu, lsum0, 2);
    lsum1 += __shfl_xor_sync(0xffffffffu, lsum1, 1);
    lsum1 += __shfl_xor_sync(0xffffffffu, lsum1, 2);
    float inv0 = 1.0f / lsum0, inv1 = 1.0f / lsum1;

    float* o0 = out + ((size_t)b * LSEQ + (size_t)qt * BQ + 16 * w + g) * DIM;
    #pragma unroll
    for (int jj = 0; jj < 16; jj++) {
        int col = 8 * jj + 2 * t4;
        *(float2*)(o0 + col) = make_float2(O[jj][0] * inv0, O[jj][1] * inv0);
        *(float2*)(o0 + 8 * DIM + col) = make_float2(O[jj][2] * inv1, O[jj][3] * inv1);
    }
}

extern "C" void kernel_launch(void* const* d_in, const int* in_sizes, int n_in,
                              void* d_out, int out_size) {
    const float* x1 = (const float*)d_in[0];
    const float* x2 = (const float*)d_in[1];
    float* out = (float*)d_out;

    cudaFuncSetAttribute(attn_mma_kernel,
                         cudaFuncAttributeMaxDynamicSharedMemorySize, SMEM_TOTAL);

    dim3 grid(LSEQ / BQ, 16);   // 16 q-tiles x 16 batches = 256 CTAs
    attn_mma_kernel<<<grid, 256, SMEM_TOTAL>>>(x1, x2, out);
}